// round 4
// baseline (speedup 1.0000x reference)
#include <cuda_runtime.h>
#include <math.h>

#define EMAX 1280
#define NMAX 384
#define NBLOCKS 96
#define TPB 128

// ---------------- persistent device scratch ----------------------------------
__device__ int      g_snd[EMAX];
__device__ int      g_rcv[EMAX];
__device__ float    g_Hd[NMAX * 5];
__device__ float    g_mi[NMAX * 5];
__device__ float    g_mo[NMAX * 5];
__device__ float2   g_ecs[9];      // cos/sin of te[10..18]
__device__ float2   g_ncs[11];     // node rotation constants (see prep)
__device__ float    g_nsum[2];     // tn13+tn18+tn22, tn14+tn19+tn28
__device__ unsigned g_cnt = 0;
__device__ unsigned g_gen = 0;

// ---------------- helpers -----------------------------------------------------
__device__ __forceinline__ void rot(float& z, float& x, float ct, float st) {
    float zn = z * ct - x * st;
    x = x * ct + z * st;
    z = zn;
}

// sense-reversing grid barrier (all NBLOCKS blocks resident by construction)
__device__ __forceinline__ void grid_bar() {
    __threadfence();
    __syncthreads();
    if (threadIdx.x == 0) {
        unsigned gen = *(volatile unsigned*)&g_gen;
        if (atomicAdd(&g_cnt, 1u) == NBLOCKS - 1) {
            atomicExch(&g_cnt, 0u);
            __threadfence();
            atomicAdd(&g_gen, 1u);
        } else {
            while (*(volatile unsigned*)&g_gen == gen) __nanosleep(32);
        }
    }
    __syncthreads();
}

// ---------------- edge circuit: exact closed-form Bloch propagation ----------
// Control DAG is a tree; CX with discarded control => z_t *= z_c.
__device__ __forceinline__ void do_edge(int k, const float* __restrict__ te,
                                        float* __restrict__ out, bool scatter) {
    int sn = g_snd[k], rc = g_rcv[k];
    float h[10], cA[10], sA[10];
#pragma unroll
    for (int j = 0; j < 5; j++) h[j]     = g_Hd[sn * 5 + j];
#pragma unroll
    for (int j = 0; j < 5; j++) h[5 + j] = g_Hd[rc * 5 + j];
#pragma unroll
    for (int j = 0; j < 10; j++) sincosf(h[j] + te[j], &sA[j], &cA[j]);

    float2 T10 = g_ecs[0], T11 = g_ecs[1], T12 = g_ecs[2], T13 = g_ecs[3];
    float2 T14 = g_ecs[4], T15 = g_ecs[5], T16 = g_ecs[6], T17 = g_ecs[7], T18 = g_ecs[8];

    // q1: init, cx0,1, ry t10
    float z1 = cA[1] * cA[0], x1 = sA[1]; rot(z1, x1, T10.x, T10.y);
    // q2: init, cx3,2, ry t11, cx1,2, ry t14
    float z2 = cA[2] * cA[3], x2 = sA[2]; rot(z2, x2, T11.x, T11.y);
    z2 *= z1;                             rot(z2, x2, T14.x, T14.y);
    // q4: init, cx5,4, ry t15, cx2,4, ry t16
    float z4 = cA[4] * cA[5], x4 = sA[4]; rot(z4, x4, T15.x, T15.y);
    z4 *= z2;                             rot(z4, x4, T16.x, T16.y);
    // q9: init, cx8,9, ry t13
    float z9 = cA[9] * cA[8], x9 = sA[9]; rot(z9, x9, T13.x, T13.y);
    // q7: init, cx6,7, ry t12, cx9,7, ry t17, cx4,7, ry t18 -> measure
    float z7 = cA[7] * cA[6], x7 = sA[7]; rot(z7, x7, T12.x, T12.y);
    z7 *= z9;                             rot(z7, x7, T17.x, T17.y);
    z7 *= z4;                             rot(z7, x7, T18.x, T18.y);

    float e = 0.5f * (1.0f - z7);
    if (scatter) {
#pragma unroll
        for (int j = 0; j < 5; j++) atomicAdd(&g_mi[rc * 5 + j], e * h[j]);
#pragma unroll
        for (int j = 0; j < 5; j++) atomicAdd(&g_mo[sn * 5 + j], e * h[5 + j]);
    }
    if (out) out[k] = e;
}

// ---------------- node circuit: closed form (A: 2-branch; B: chain) ----------
__device__ __forceinline__ void do_node(int n, const float* __restrict__ tn) {
    float f[15];
#pragma unroll
    for (int j = 0; j < 5; j++) f[j]      = g_mi[n * 5 + j];
#pragma unroll
    for (int j = 0; j < 5; j++) f[5 + j]  = g_mo[n * 5 + j];
#pragma unroll
    for (int j = 0; j < 5; j++) f[10 + j] = g_Hd[n * 5 + j];
    // re-zero messages for the next edge round (exclusive slots)
#pragma unroll
    for (int j = 0; j < 5; j++) { g_mi[n * 5 + j] = 0.f; g_mo[n * 5 + j] = 0.f; }

    float2 R;
    // ---- component B: <Z10>. cx8,9 pairs and cx9,10 pairs cancel; q8,q9,q12 drop.
    float cA10, sA10; sincosf(f[10] + tn[10], &sA10, &cA10);
    float z11 = cosf(f[11] + tn[11]);
    float z13 = cosf(f[13] + g_nsum[0]);   // q13: f + t13+t18+t22
    float z14 = cosf(f[14] + g_nsum[1]);   // q14: f + t14+t19+t28
    float zb = cA10 * z11, xb = sA10;      // init, cx11,10
    R = g_ncs[8];  rot(zb, xb, R.x, R.y);  // t17+t21
    zb *= z13;                             // cx13,10
    R = g_ncs[9];  rot(zb, xb, R.x, R.y);  // t24+t27
    zb *= z14;                             // cx14,10
    R = g_ncs[10]; rot(zb, xb, R.x, R.y);  // t30
    float zB = zb;

    // ---- component A: <Z5>, branch over dephased q1 bit (carries q0 coherence)
    float a0 = 0.5f * (f[0] + tn[0]);
    float a1 = 0.5f * (f[1] + tn[1]);
    float t15h = 0.5f * tn[15];
    float cg0, sg0; sincosf(t15h + a1, &sg0, &cg0);        // gamma_0
    float cd, sd;   sincosf(t15h - a1, &sd, &cd);
    float cg1 = -sd, sg1 = cd;                              // gamma_1 = t15h+pi/2-a1
    float ca0, sa0; sincosf(a0, &sa0, &ca0);
    float2 R25 = g_ncs[7];                                  // cos/sin(t25/2)
    float w[2], zw[2];
    {
        float p0 = ca0 * cg0, p1 = sa0 * cg1;               // beta1 = 0
        float q0 = p0 * R25.x - p1 * R25.y, q1 = p1 * R25.x + p0 * R25.y;
        w[0] = q0 * q0 + q1 * q1;  zw[0] = q0 * q0 - q1 * q1;
        p0 = ca0 * sg0;  p1 = sa0 * sg1;                    // beta1 = 1
        q0 = p0 * R25.x - p1 * R25.y;  q1 = p1 * R25.x + p0 * R25.y;
        w[1] = q0 * q0 + q1 * q1;  zw[1] = q0 * q0 - q1 * q1;
    }
    // q2: init, cx3,2, t16, X^{beta1}, t19 -> control of cx2,5
    float cA2, sA2; sincosf(f[2] + tn[2], &sA2, &cA2);
    float z3 = cosf(f[3] + tn[3]);
    float z2 = cA2 * z3, x2 = sA2;
    R = g_ncs[0]; rot(z2, x2, R.x, R.y);                    // t16
    float2 R19 = g_ncs[1];
    float z2b0 =  z2, x2b0 = x2; rot(z2b0, x2b0, R19.x, R19.y);
    float z2b1 = -z2, x2b1 = x2; rot(z2b1, x2b1, R19.x, R19.y);
    (void)x2b0; (void)x2b1;
    // q6: init, cx7,6, t15 -> control of cx6,5
    float cA6, sA6; sincosf(f[6] + tn[6], &sA6, &cA6);
    float z7c = cosf(f[7] + tn[7]);
    float z6 = cA6 * z7c, x6 = sA6;
    R = g_ncs[3]; rot(z6, x6, R.x, R.y);                    // t15
    // q5 common: init, cx4,5, t14, cx6,5, t20
    float cA5, sA5; sincosf(f[5] + tn[5], &sA5, &cA5);
    float z4c = cosf(f[4] + tn[4]);
    float z5 = cA5 * z4c, x5 = sA5;
    R = g_ncs[2]; rot(z5, x5, R.x, R.y);                    // t14
    z5 *= z6;
    R = g_ncs[4]; rot(z5, x5, R.x, R.y);                    // t20
    float2 R2326 = g_ncs[5], R29 = g_ncs[6];
    float zA = 0.f;
#pragma unroll
    for (int b = 0; b < 2; b++) {
        float z = z5 * (b ? z2b1 : z2b0), x = x5;           // cx2,5
        rot(z, x, R2326.x, R2326.y);                        // t23 + t26
        float zp = z * zw[b], xp = x * w[b];                // cx0,5 (weighted)
        zA += zp * R29.x - xp * R29.y;                      // t29, take z
    }
    const float PI_F = 3.14159265358979f;
    g_Hd[n * 5 + 0] = PI_F * (1.f - zA);
    g_Hd[n * 5 + 1] = PI_F * (1.f - zB);
}

// ---------------- fused persistent kernel ------------------------------------
__global__ void __launch_bounds__(TPB) gnn_fused(
    const float* __restrict__ X, const float* __restrict__ Ri,
    const float* __restrict__ Ro, const float* __restrict__ W,
    const float* __restrict__ te, const float* __restrict__ tn,
    float* __restrict__ out, int N, int E) {
    int gt = blockIdx.x * TPB + threadIdx.x;

    // ---------------- phase 0: prep ----------------
    int quarter = (N * E) >> 2;
    for (int i = gt; i < 2 * quarter; i += NBLOCKS * TPB) {
        if (i < quarter) {
            float4 v = ((const float4*)Ro)[i];
            int base = i * 4;
            if (v.x > 0.5f) g_snd[ base      % E] =  base      / E;
            if (v.y > 0.5f) g_snd[(base + 1) % E] = (base + 1) / E;
            if (v.z > 0.5f) g_snd[(base + 2) % E] = (base + 2) / E;
            if (v.w > 0.5f) g_snd[(base + 3) % E] = (base + 3) / E;
        } else {
            int u = i - quarter;
            float4 v = ((const float4*)Ri)[u];
            int base = u * 4;
            if (v.x > 0.5f) g_rcv[ base      % E] =  base      / E;
            if (v.y > 0.5f) g_rcv[(base + 1) % E] = (base + 1) / E;
            if (v.z > 0.5f) g_rcv[(base + 2) % E] = (base + 2) / E;
            if (v.w > 0.5f) g_rcv[(base + 3) % E] = (base + 3) / E;
        }
    }
    if (gt < N * 5) { g_mi[gt] = 0.f; g_mo[gt] = 0.f; }
    if (gt < N) {
        float x0 = X[gt * 3 + 0], x1 = X[gt * 3 + 1], x2 = X[gt * 3 + 2];
        float z0 = x0 * W[0] + x1 * W[2] + x2 * W[4];
        float z1 = x0 * W[1] + x1 * W[3] + x2 * W[5];
        const float TWOPI = 6.283185307179586f;
        g_Hd[gt * 5 + 0] = TWOPI / (1.f + expf(-z0));
        g_Hd[gt * 5 + 1] = TWOPI / (1.f + expf(-z1));
        g_Hd[gt * 5 + 2] = x0;
        g_Hd[gt * 5 + 3] = x1;
        g_Hd[gt * 5 + 4] = x2;
    }
    if (gt >= 128 && gt < 137) {           // edge rotation constants te[10..18]
        int i = gt - 128;
        float ss, cc; sincosf(te[10 + i], &ss, &cc);
        g_ecs[i] = make_float2(cc, ss);
    }
    if (gt >= 160 && gt < 171) {           // node rotation constants
        int i = gt - 160; float ang = 0.f;
        switch (i) {
            case 0:  ang = tn[16]; break;
            case 1:  ang = tn[19]; break;
            case 2:  ang = tn[14]; break;
            case 3:  ang = tn[15]; break;
            case 4:  ang = tn[20]; break;
            case 5:  ang = tn[23] + tn[26]; break;
            case 6:  ang = tn[29]; break;
            case 7:  ang = 0.5f * tn[25]; break;
            case 8:  ang = tn[17] + tn[21]; break;
            case 9:  ang = tn[24] + tn[27]; break;
            case 10: ang = tn[30]; break;
        }
        float ss, cc; sincosf(ang, &ss, &cc);
        g_ncs[i] = make_float2(cc, ss);
    }
    if (gt == 192) g_nsum[0] = tn[13] + tn[18] + tn[22];
    if (gt == 193) g_nsum[1] = tn[14] + tn[19] + tn[28];

    grid_bar();

    // ---------------- iterate: edge, node, edge, node, edge ----------------
    int epb = (E + NBLOCKS - 1) / NBLOCKS;   // edges per block (14)
    int npb = (N + NBLOCKS - 1) / NBLOCKS;   // nodes per block (4)

    for (int it = 0; it < 3; it++) {
        int k = blockIdx.x * epb + threadIdx.x;
        if (threadIdx.x < epb && k < E)
            do_edge(k, te, (it == 2) ? out : nullptr, it < 2);
        if (it < 2) {
            grid_bar();
            int n = blockIdx.x * npb + threadIdx.x;
            if (threadIdx.x < npb && n < N)
                do_node(n, tn);
            grid_bar();
        }
    }
}

// ---------------- launch (graph-capturable, single kernel) -------------------
extern "C" void kernel_launch(void* const* d_in, const int* in_sizes, int n_in,
                              void* d_out, int out_size) {
    const float* X  = (const float*)d_in[0];
    const float* Ri = (const float*)d_in[1];
    const float* Ro = (const float*)d_in[2];
    const float* W  = (const float*)d_in[3];
    const float* te = (const float*)d_in[4];
    const float* tn = (const float*)d_in[5];
    int N = in_sizes[0] / 3;
    int E = in_sizes[1] / N;

    gnn_fused<<<NBLOCKS, TPB>>>(X, Ri, Ro, W, te, tn, (float*)d_out, N, E);
}

// round 5
// speedup vs baseline: 1.3588x; 1.3588x over previous
#include <cuda_runtime.h>
#include <math.h>

#define EMAX 1280
#define NMAX 384

// ---------------- persistent device scratch ----------------------------------
__device__ int    g_snd[EMAX];
__device__ int    g_rcv[EMAX];
__device__ float  g_Hd[NMAX * 5];
__device__ float  g_mi[NMAX * 5];
__device__ float  g_mo[NMAX * 5];
__device__ float2 g_ecs[9];      // cos/sin of te[10..18]
__device__ float2 g_ncs[11];     // node rotation constants
__device__ float  g_nsum[2];     // tn13+tn18+tn22, tn14+tn19+tn28

// ---------------- helpers -----------------------------------------------------
__device__ __forceinline__ void rot(float& z, float& x, float ct, float st) {
    float zn = z * ct - x * st;
    x = x * ct + z * st;
    z = zn;
}

// ---------------- prep (wide): extract, H0, constants ------------------------
__global__ void prep_kernel(const float* __restrict__ X, const float* __restrict__ Ri,
                            const float* __restrict__ Ro, const float* __restrict__ W,
                            const float* __restrict__ te, const float* __restrict__ tn,
                            int N, int E) {
    int t = blockIdx.x * blockDim.x + threadIdx.x;
    int quarter = (N * E) >> 2;
    if (t < quarter) {
        float4 v = ((const float4*)Ro)[t];
        int base = t * 4;
        if (v.x > 0.5f) g_snd[ base      % E] =  base      / E;
        if (v.y > 0.5f) g_snd[(base + 1) % E] = (base + 1) / E;
        if (v.z > 0.5f) g_snd[(base + 2) % E] = (base + 2) / E;
        if (v.w > 0.5f) g_snd[(base + 3) % E] = (base + 3) / E;
    } else if (t < 2 * quarter) {
        int u = t - quarter;
        float4 v = ((const float4*)Ri)[u];
        int base = u * 4;
        if (v.x > 0.5f) g_rcv[ base      % E] =  base      / E;
        if (v.y > 0.5f) g_rcv[(base + 1) % E] = (base + 1) / E;
        if (v.z > 0.5f) g_rcv[(base + 2) % E] = (base + 2) / E;
        if (v.w > 0.5f) g_rcv[(base + 3) % E] = (base + 3) / E;
    }
    if (t < N * 5) { g_mi[t] = 0.f; g_mo[t] = 0.f; }
    if (t < N) {
        float x0 = X[t * 3 + 0], x1 = X[t * 3 + 1], x2 = X[t * 3 + 2];
        float z0 = x0 * W[0] + x1 * W[2] + x2 * W[4];
        float z1 = x0 * W[1] + x1 * W[3] + x2 * W[5];
        const float TWOPI = 6.283185307179586f;
        g_Hd[t * 5 + 0] = TWOPI / (1.f + expf(-z0));
        g_Hd[t * 5 + 1] = TWOPI / (1.f + expf(-z1));
        g_Hd[t * 5 + 2] = x0;
        g_Hd[t * 5 + 3] = x1;
        g_Hd[t * 5 + 4] = x2;
    }
    if (t >= 512 && t < 521) {          // edge rotation constants te[10..18]
        int i = t - 512;
        float ss, cc; sincosf(te[10 + i], &ss, &cc);
        g_ecs[i] = make_float2(cc, ss);
    }
    if (t >= 544 && t < 555) {          // node rotation constants
        int i = t - 544; float ang = 0.f;
        switch (i) {
            case 0:  ang = tn[16]; break;
            case 1:  ang = tn[19]; break;
            case 2:  ang = tn[14]; break;
            case 3:  ang = tn[15]; break;
            case 4:  ang = tn[20]; break;
            case 5:  ang = tn[23] + tn[26]; break;
            case 6:  ang = tn[29]; break;
            case 7:  ang = 0.5f * tn[25]; break;
            case 8:  ang = tn[17] + tn[21]; break;
            case 9:  ang = tn[24] + tn[27]; break;
            case 10: ang = tn[30]; break;
        }
        float ss, cc; sincosf(ang, &ss, &cc);
        g_ncs[i] = make_float2(cc, ss);
    }
    if (t == 576) g_nsum[0] = tn[13] + tn[18] + tn[22];
    if (t == 577) g_nsum[1] = tn[14] + tn[19] + tn[28];
}

// ---------------- edge kernel: one thread per edge, closed-form --------------
// Control DAG is a tree; CX with discarded control => z_t *= z_c.
__global__ void edge_kernel(const float* __restrict__ te, int E,
                            float* __restrict__ out, int scatter) {
    int k = blockIdx.x * blockDim.x + threadIdx.x;
    if (k >= E) return;
    int sn = g_snd[k], rc = g_rcv[k];
    float h[10], cA[10], sA[10];
#pragma unroll
    for (int j = 0; j < 5; j++) h[j]     = g_Hd[sn * 5 + j];
#pragma unroll
    for (int j = 0; j < 5; j++) h[5 + j] = g_Hd[rc * 5 + j];
#pragma unroll
    for (int j = 0; j < 10; j++) sincosf(h[j] + te[j], &sA[j], &cA[j]);

    float2 T10 = g_ecs[0], T11 = g_ecs[1], T12 = g_ecs[2], T13 = g_ecs[3];
    float2 T14 = g_ecs[4], T15 = g_ecs[5], T16 = g_ecs[6], T17 = g_ecs[7], T18 = g_ecs[8];

    // q1: init, cx0,1, ry t10
    float z1 = cA[1] * cA[0], x1 = sA[1]; rot(z1, x1, T10.x, T10.y);
    // q2: init, cx3,2, ry t11, cx1,2, ry t14
    float z2 = cA[2] * cA[3], x2 = sA[2]; rot(z2, x2, T11.x, T11.y);
    z2 *= z1;                             rot(z2, x2, T14.x, T14.y);
    // q4: init, cx5,4, ry t15, cx2,4, ry t16
    float z4 = cA[4] * cA[5], x4 = sA[4]; rot(z4, x4, T15.x, T15.y);
    z4 *= z2;                             rot(z4, x4, T16.x, T16.y);
    // q9: init, cx8,9, ry t13
    float z9 = cA[9] * cA[8], x9 = sA[9]; rot(z9, x9, T13.x, T13.y);
    // q7: init, cx6,7, ry t12, cx9,7, ry t17, cx4,7, ry t18 -> measure
    float z7 = cA[7] * cA[6], x7 = sA[7]; rot(z7, x7, T12.x, T12.y);
    z7 *= z9;                             rot(z7, x7, T17.x, T17.y);
    z7 *= z4;                             rot(z7, x7, T18.x, T18.y);

    float e = 0.5f * (1.0f - z7);
    if (scatter) {
#pragma unroll
        for (int j = 0; j < 5; j++) atomicAdd(&g_mi[rc * 5 + j], e * h[j]);
#pragma unroll
        for (int j = 0; j < 5; j++) atomicAdd(&g_mo[sn * 5 + j], e * h[5 + j]);
    }
    if (out) out[k] = e;
}

// ---------------- node kernel: one thread per node, closed-form --------------
__global__ void node_kernel(const float* __restrict__ tn, int N) {
    int n = blockIdx.x * blockDim.x + threadIdx.x;
    if (n >= N) return;
    float f[15];
#pragma unroll
    for (int j = 0; j < 5; j++) f[j]      = g_mi[n * 5 + j];
#pragma unroll
    for (int j = 0; j < 5; j++) f[5 + j]  = g_mo[n * 5 + j];
#pragma unroll
    for (int j = 0; j < 5; j++) f[10 + j] = g_Hd[n * 5 + j];
    // re-zero messages for the next edge round (exclusive slots)
#pragma unroll
    for (int j = 0; j < 5; j++) { g_mi[n * 5 + j] = 0.f; g_mo[n * 5 + j] = 0.f; }

    float2 R;
    // ---- component B: <Z10>. cx8,9 pairs and cx9,10 pairs cancel; q8,q9,q12 drop.
    float cA10, sA10; sincosf(f[10] + tn[10], &sA10, &cA10);
    float z11 = cosf(f[11] + tn[11]);
    float z13 = cosf(f[13] + g_nsum[0]);
    float z14 = cosf(f[14] + g_nsum[1]);
    float zb = cA10 * z11, xb = sA10;      // init, cx11,10
    R = g_ncs[8];  rot(zb, xb, R.x, R.y);  // t17+t21
    zb *= z13;                             // cx13,10
    R = g_ncs[9];  rot(zb, xb, R.x, R.y);  // t24+t27
    zb *= z14;                             // cx14,10
    R = g_ncs[10]; rot(zb, xb, R.x, R.y);  // t30
    float zB = zb;

    // ---- component A: <Z5>, branch over dephased q1 bit (carries q0 coherence)
    float a0 = 0.5f * (f[0] + tn[0]);
    float a1 = 0.5f * (f[1] + tn[1]);
    float t15h = 0.5f * tn[15];
    float cg0, sg0; sincosf(t15h + a1, &sg0, &cg0);
    float cd, sd;   sincosf(t15h - a1, &sd, &cd);
    float cg1 = -sd, sg1 = cd;
    float ca0, sa0; sincosf(a0, &sa0, &ca0);
    float2 R25 = g_ncs[7];
    float w[2], zw[2];
    {
        float p0 = ca0 * cg0, p1 = sa0 * cg1;
        float q0 = p0 * R25.x - p1 * R25.y, q1 = p1 * R25.x + p0 * R25.y;
        w[0] = q0 * q0 + q1 * q1;  zw[0] = q0 * q0 - q1 * q1;
        p0 = ca0 * sg0;  p1 = sa0 * sg1;
        q0 = p0 * R25.x - p1 * R25.y;  q1 = p1 * R25.x + p0 * R25.y;
        w[1] = q0 * q0 + q1 * q1;  zw[1] = q0 * q0 - q1 * q1;
    }
    // q2: init, cx3,2, t16, X^{beta1}, t19 -> control of cx2,5
    float cA2, sA2; sincosf(f[2] + tn[2], &sA2, &cA2);
    float z3 = cosf(f[3] + tn[3]);
    float z2 = cA2 * z3, x2 = sA2;
    R = g_ncs[0]; rot(z2, x2, R.x, R.y);                    // t16
    float2 R19 = g_ncs[1];
    float z2b0 =  z2, x2b0 = x2; rot(z2b0, x2b0, R19.x, R19.y);
    float z2b1 = -z2, x2b1 = x2; rot(z2b1, x2b1, R19.x, R19.y);
    // q6: init, cx7,6, t15 -> control of cx6,5
    float cA6, sA6; sincosf(f[6] + tn[6], &sA6, &cA6);
    float z7c = cosf(f[7] + tn[7]);
    float z6 = cA6 * z7c, x6 = sA6;
    R = g_ncs[3]; rot(z6, x6, R.x, R.y);                    // t15
    // q5 common: init, cx4,5, t14, cx6,5, t20
    float cA5, sA5; sincosf(f[5] + tn[5], &sA5, &cA5);
    float z4c = cosf(f[4] + tn[4]);
    float z5 = cA5 * z4c, x5 = sA5;
    R = g_ncs[2]; rot(z5, x5, R.x, R.y);                    // t14
    z5 *= z6;
    R = g_ncs[4]; rot(z5, x5, R.x, R.y);                    // t20
    float2 R2326 = g_ncs[5], R29 = g_ncs[6];
    float zA = 0.f;
#pragma unroll
    for (int b = 0; b < 2; b++) {
        float z = z5 * (b ? z2b1 : z2b0), x = x5;           // cx2,5
        rot(z, x, R2326.x, R2326.y);                        // t23 + t26
        float zp = z * zw[b], xp = x * w[b];                // cx0,5 (weighted)
        zA += zp * R29.x - xp * R29.y;                      // t29, take z
    }
    const float PI_F = 3.14159265358979f;
    g_Hd[n * 5 + 0] = PI_F * (1.f - zA);
    g_Hd[n * 5 + 1] = PI_F * (1.f - zB);
}

// ---------------- launch sequence (graph-capturable, 6 kernels) --------------
extern "C" void kernel_launch(void* const* d_in, const int* in_sizes, int n_in,
                              void* d_out, int out_size) {
    const float* X  = (const float*)d_in[0];
    const float* Ri = (const float*)d_in[1];
    const float* Ro = (const float*)d_in[2];
    const float* W  = (const float*)d_in[3];
    const float* te = (const float*)d_in[4];
    const float* tn = (const float*)d_in[5];
    int N = in_sizes[0] / 3;
    int E = in_sizes[1] / N;
    float* out = (float*)d_out;

    int pg = (2 * ((N * E) / 4) + 255) / 256;   // float4 scan of Ro + Ri
    int eb = (E + 127) / 128;                   // one thread per edge
    int nb = (N + 127) / 128;                   // one thread per node

    prep_kernel<<<pg, 256>>>(X, Ri, Ro, W, te, tn, N, E);
    edge_kernel<<<eb, 128>>>(te, E, nullptr, 1);
    node_kernel<<<nb, 128>>>(tn, N);
    edge_kernel<<<eb, 128>>>(te, E, nullptr, 1);
    node_kernel<<<nb, 128>>>(tn, N);
    edge_kernel<<<eb, 128>>>(te, E, out, 0);
}

// round 6
// speedup vs baseline: 1.5008x; 1.1045x over previous
#include <cuda_runtime.h>
#include <math.h>

#define EMAX 1280
#define NMAX 384
#define HS 8            // padded row stride for H / mi / mo

// ---------------- persistent device scratch ----------------------------------
__device__ int    g_snd[EMAX];
__device__ int    g_rcv[EMAX];
__device__ float  g_Hd[NMAX * HS];
__device__ float  g_mi[NMAX * HS];
__device__ float  g_mo[NMAX * HS];
__device__ float2 g_ecs[9];      // cos/sin of te[10..18]
__device__ float2 g_ncs[11];     // node rotation constants
__device__ float  g_nsum[2];     // tn13+tn18+tn22, tn14+tn19+tn28

// ---------------- helpers -----------------------------------------------------
__device__ __forceinline__ void rot(float& z, float& x, float ct, float st) {
    float zn = z * ct - x * st;
    x = x * ct + z * st;
    z = zn;
}

// ---------------- prep (wide): extract, H0, constants ------------------------
__global__ void prep_kernel(const float* __restrict__ X, const float* __restrict__ Ri,
                            const float* __restrict__ Ro, const float* __restrict__ W,
                            const float* __restrict__ te, const float* __restrict__ tn,
                            int N, int E) {
    int t = blockIdx.x * blockDim.x + threadIdx.x;
    int quarter = (N * E) >> 2;
    if (t < quarter) {
        float4 v = ((const float4*)Ro)[t];
        int base = t * 4;
        if (v.x > 0.5f) g_snd[ base      % E] =  base      / E;
        if (v.y > 0.5f) g_snd[(base + 1) % E] = (base + 1) / E;
        if (v.z > 0.5f) g_snd[(base + 2) % E] = (base + 2) / E;
        if (v.w > 0.5f) g_snd[(base + 3) % E] = (base + 3) / E;
    } else if (t < 2 * quarter) {
        int u = t - quarter;
        float4 v = ((const float4*)Ri)[u];
        int base = u * 4;
        if (v.x > 0.5f) g_rcv[ base      % E] =  base      / E;
        if (v.y > 0.5f) g_rcv[(base + 1) % E] = (base + 1) / E;
        if (v.z > 0.5f) g_rcv[(base + 2) % E] = (base + 2) / E;
        if (v.w > 0.5f) g_rcv[(base + 3) % E] = (base + 3) / E;
    }
    if (t < N * HS) { g_mi[t] = 0.f; g_mo[t] = 0.f; }
    if (t < N) {
        float x0 = X[t * 3 + 0], x1 = X[t * 3 + 1], x2 = X[t * 3 + 2];
        float z0 = x0 * W[0] + x1 * W[2] + x2 * W[4];
        float z1 = x0 * W[1] + x1 * W[3] + x2 * W[5];
        const float TWOPI = 6.283185307179586f;
        g_Hd[t * HS + 0] = TWOPI / (1.f + __expf(-z0));
        g_Hd[t * HS + 1] = TWOPI / (1.f + __expf(-z1));
        g_Hd[t * HS + 2] = x0;
        g_Hd[t * HS + 3] = x1;
        g_Hd[t * HS + 4] = x2;
        g_Hd[t * HS + 5] = 0.f;
        g_Hd[t * HS + 6] = 0.f;
        g_Hd[t * HS + 7] = 0.f;
    }
    if (t >= 3072 && t < 3081) {        // edge rotation constants te[10..18]
        int i = t - 3072;
        float ss, cc; sincosf(te[10 + i], &ss, &cc);
        g_ecs[i] = make_float2(cc, ss);
    }
    if (t >= 3104 && t < 3115) {        // node rotation constants
        int i = t - 3104; float ang = 0.f;
        switch (i) {
            case 0:  ang = tn[16]; break;
            case 1:  ang = tn[19]; break;
            case 2:  ang = tn[14]; break;
            case 3:  ang = tn[15]; break;
            case 4:  ang = tn[20]; break;
            case 5:  ang = tn[23] + tn[26]; break;
            case 6:  ang = tn[29]; break;
            case 7:  ang = 0.5f * tn[25]; break;
            case 8:  ang = tn[17] + tn[21]; break;
            case 9:  ang = tn[24] + tn[27]; break;
            case 10: ang = tn[30]; break;
        }
        float ss, cc; sincosf(ang, &ss, &cc);
        g_ncs[i] = make_float2(cc, ss);
    }
    if (t == 3136) g_nsum[0] = tn[13] + tn[18] + tn[22];
    if (t == 3137) g_nsum[1] = tn[14] + tn[19] + tn[28];
}

// ---------------- edge kernel: one thread per edge, closed-form --------------
// Control DAG is a tree; CX with discarded control => z_t *= z_c.
__global__ void edge_kernel(const float* __restrict__ te, int E,
                            float* __restrict__ out, int scatter) {
    int k = blockIdx.x * blockDim.x + threadIdx.x;
    if (k >= E) return;
    int sn = g_snd[k], rc = g_rcv[k];

    float h[10];
    {   // padded rows: float4 + scalar per endpoint
        float4 v0 = *(const float4*)&g_Hd[sn * HS];
        float4 v1 = *(const float4*)&g_Hd[rc * HS];
        h[0] = v0.x; h[1] = v0.y; h[2] = v0.z; h[3] = v0.w; h[4] = g_Hd[sn * HS + 4];
        h[5] = v1.x; h[6] = v1.y; h[7] = v1.z; h[8] = v1.w; h[9] = g_Hd[rc * HS + 4];
    }
    float cA[10], sA[10];
#pragma unroll
    for (int j = 0; j < 10; j++) __sincosf(h[j] + te[j], &sA[j], &cA[j]);

    float2 T10 = g_ecs[0], T11 = g_ecs[1], T12 = g_ecs[2], T13 = g_ecs[3];
    float2 T14 = g_ecs[4], T15 = g_ecs[5], T16 = g_ecs[6], T17 = g_ecs[7], T18 = g_ecs[8];

    // q1: init, cx0,1, ry t10
    float z1 = cA[1] * cA[0], x1 = sA[1]; rot(z1, x1, T10.x, T10.y);
    // q2: init, cx3,2, ry t11, cx1,2, ry t14
    float z2 = cA[2] * cA[3], x2 = sA[2]; rot(z2, x2, T11.x, T11.y);
    z2 *= z1;                             rot(z2, x2, T14.x, T14.y);
    // q4: init, cx5,4, ry t15, cx2,4, ry t16
    float z4 = cA[4] * cA[5], x4 = sA[4]; rot(z4, x4, T15.x, T15.y);
    z4 *= z2;                             rot(z4, x4, T16.x, T16.y);
    // q9: init, cx8,9, ry t13
    float z9 = cA[9] * cA[8], x9 = sA[9]; rot(z9, x9, T13.x, T13.y);
    // q7: init, cx6,7, ry t12, cx9,7, ry t17, cx4,7, ry t18 -> measure
    float z7 = cA[7] * cA[6], x7 = sA[7]; rot(z7, x7, T12.x, T12.y);
    z7 *= z9;                             rot(z7, x7, T17.x, T17.y);
    z7 *= z4;                             rot(z7, x7, T18.x, T18.y);

    float e = 0.5f * (1.0f - z7);
    if (scatter) {
#pragma unroll
        for (int j = 0; j < 5; j++) atomicAdd(&g_mi[rc * HS + j], e * h[j]);
#pragma unroll
        for (int j = 0; j < 5; j++) atomicAdd(&g_mo[sn * HS + j], e * h[5 + j]);
    }
    if (out) out[k] = e;
}

// ---------------- node kernel: one thread per node, closed-form --------------
__global__ void node_kernel(const float* __restrict__ tn, int N) {
    int n = blockIdx.x * blockDim.x + threadIdx.x;
    if (n >= N) return;
    float f[15];
    {
        float4 a = *(const float4*)&g_mi[n * HS];
        f[0] = a.x; f[1] = a.y; f[2] = a.z; f[3] = a.w; f[4] = g_mi[n * HS + 4];
        float4 b = *(const float4*)&g_mo[n * HS];
        f[5] = b.x; f[6] = b.y; f[7] = b.z; f[8] = b.w; f[9] = g_mo[n * HS + 4];
        float4 d = *(const float4*)&g_Hd[n * HS];
        f[10] = d.x; f[11] = d.y; f[12] = d.z; f[13] = d.w; f[14] = g_Hd[n * HS + 4];
    }
    // re-zero messages for the next edge round (exclusive slots)
    *(float4*)&g_mi[n * HS] = make_float4(0.f, 0.f, 0.f, 0.f);
    g_mi[n * HS + 4] = 0.f;
    *(float4*)&g_mo[n * HS] = make_float4(0.f, 0.f, 0.f, 0.f);
    g_mo[n * HS + 4] = 0.f;

    float2 R;
    // ---- component B: <Z10>. cx8,9 pairs and cx9,10 pairs cancel; q8,q9,q12 drop.
    float cA10, sA10; __sincosf(f[10] + tn[10], &sA10, &cA10);
    float z11 = __cosf(f[11] + tn[11]);
    float z13 = __cosf(f[13] + g_nsum[0]);
    float z14 = __cosf(f[14] + g_nsum[1]);
    float zb = cA10 * z11, xb = sA10;      // init, cx11,10
    R = g_ncs[8];  rot(zb, xb, R.x, R.y);  // t17+t21
    zb *= z13;                             // cx13,10
    R = g_ncs[9];  rot(zb, xb, R.x, R.y);  // t24+t27
    zb *= z14;                             // cx14,10
    R = g_ncs[10]; rot(zb, xb, R.x, R.y);  // t30
    float zB = zb;

    // ---- component A: <Z5>, branch over dephased q1 bit (carries q0 coherence)
    float a0 = 0.5f * (f[0] + tn[0]);
    float a1 = 0.5f * (f[1] + tn[1]);
    float t15h = 0.5f * tn[15];
    float cg0, sg0; __sincosf(t15h + a1, &sg0, &cg0);
    float cd, sd;   __sincosf(t15h - a1, &sd, &cd);
    float cg1 = -sd, sg1 = cd;
    float ca0, sa0; __sincosf(a0, &sa0, &ca0);
    float2 R25 = g_ncs[7];
    float w[2], zw[2];
    {
        float p0 = ca0 * cg0, p1 = sa0 * cg1;
        float q0 = p0 * R25.x - p1 * R25.y, q1 = p1 * R25.x + p0 * R25.y;
        w[0] = q0 * q0 + q1 * q1;  zw[0] = q0 * q0 - q1 * q1;
        p0 = ca0 * sg0;  p1 = sa0 * sg1;
        q0 = p0 * R25.x - p1 * R25.y;  q1 = p1 * R25.x + p0 * R25.y;
        w[1] = q0 * q0 + q1 * q1;  zw[1] = q0 * q0 - q1 * q1;
    }
    // q2: init, cx3,2, t16, X^{beta1}, t19 -> control of cx2,5
    float cA2, sA2; __sincosf(f[2] + tn[2], &sA2, &cA2);
    float z3 = __cosf(f[3] + tn[3]);
    float z2 = cA2 * z3, x2 = sA2;
    R = g_ncs[0]; rot(z2, x2, R.x, R.y);                    // t16
    float2 R19 = g_ncs[1];
    float z2b0 =  z2, x2b0 = x2; rot(z2b0, x2b0, R19.x, R19.y);
    float z2b1 = -z2, x2b1 = x2; rot(z2b1, x2b1, R19.x, R19.y);
    // q6: init, cx7,6, t15 -> control of cx6,5
    float cA6, sA6; __sincosf(f[6] + tn[6], &sA6, &cA6);
    float z7c = __cosf(f[7] + tn[7]);
    float z6 = cA6 * z7c, x6 = sA6;
    R = g_ncs[3]; rot(z6, x6, R.x, R.y);                    // t15
    // q5 common: init, cx4,5, t14, cx6,5, t20
    float cA5, sA5; __sincosf(f[5] + tn[5], &sA5, &cA5);
    float z4c = __cosf(f[4] + tn[4]);
    float z5 = cA5 * z4c, x5 = sA5;
    R = g_ncs[2]; rot(z5, x5, R.x, R.y);                    // t14
    z5 *= z6;
    R = g_ncs[4]; rot(z5, x5, R.x, R.y);                    // t20
    float2 R2326 = g_ncs[5], R29 = g_ncs[6];
    float zA = 0.f;
#pragma unroll
    for (int b = 0; b < 2; b++) {
        float z = z5 * (b ? z2b1 : z2b0), x = x5;           // cx2,5
        rot(z, x, R2326.x, R2326.y);                        // t23 + t26
        float zp = z * zw[b], xp = x * w[b];                // cx0,5 (weighted)
        zA += zp * R29.x - xp * R29.y;                      // t29, take z
    }
    const float PI_F = 3.14159265358979f;
    g_Hd[n * HS + 0] = PI_F * (1.f - zA);
    g_Hd[n * HS + 1] = PI_F * (1.f - zB);
}

// ---------------- launch sequence (graph-capturable, 6 kernels) --------------
extern "C" void kernel_launch(void* const* d_in, const int* in_sizes, int n_in,
                              void* d_out, int out_size) {
    const float* X  = (const float*)d_in[0];
    const float* Ri = (const float*)d_in[1];
    const float* Ro = (const float*)d_in[2];
    const float* W  = (const float*)d_in[3];
    const float* te = (const float*)d_in[4];
    const float* tn = (const float*)d_in[5];
    int N = in_sizes[0] / 3;
    int E = in_sizes[1] / N;
    float* out = (float*)d_out;

    int pg = (2 * ((N * E) / 4) + 255) / 256;   // float4 scan of Ro + Ri
    int eb = (E + 255) / 256;                   // one thread per edge, 2 warps/SMSP
    int nb = (N + 191) / 192;                   // one thread per node

    prep_kernel<<<pg, 256>>>(X, Ri, Ro, W, te, tn, N, E);
    edge_kernel<<<eb, 256>>>(te, E, nullptr, 1);
    node_kernel<<<nb, 192>>>(tn, N);
    edge_kernel<<<eb, 256>>>(te, E, nullptr, 1);
    node_kernel<<<nb, 192>>>(tn, N);
    edge_kernel<<<eb, 256>>>(te, E, out, 0);
}

// round 8
// speedup vs baseline: 1.5927x; 1.0613x over previous
#include <cuda_runtime.h>
#include <math.h>

#define EMAX 1280
#define NMAX 384
#define HS 8            // padded row stride for H / mi / mo
#define NBLOCKS 120     // < SM count -> all blocks co-resident (1 block/SM)
#define TPB 256

// ---------------- persistent device scratch ----------------------------------
__device__ int      g_snd[EMAX];
__device__ int      g_rcv[EMAX];
__device__ float    g_Hd[NMAX * HS];
__device__ float    g_mi[NMAX * HS];
__device__ float    g_mo[NMAX * HS];
__device__ float2   g_ecs[9];      // cos/sin of te[10..18]
__device__ float2   g_ncs[11];     // node rotation constants
__device__ float    g_nsum[2];     // tn13+tn18+tn22, tn14+tn19+tn28
__device__ unsigned g_bar[4];      // one-shot barrier counters (reset by prep)

// ---------------- helpers -----------------------------------------------------
__device__ __forceinline__ void rot(float& z, float& x, float ct, float st) {
    float zn = z * ct - x * st;
    x = x * ct + z * st;
    z = zn;
}

// one-shot grid barrier #i (counters zeroed by prep each replay)
__device__ __forceinline__ void gbar(int i) {
    __syncthreads();
    if (threadIdx.x == 0) {
        __threadfence();                       // publish this block's writes
        atomicAdd(&g_bar[i], 1u);
        while (((volatile unsigned*)g_bar)[i] < NBLOCKS) __nanosleep(20);
    }
    __syncthreads();
}

// ---------------- prep (wide): extract, H0, constants, bar reset -------------
__global__ void prep_kernel(const float* __restrict__ X, const float* __restrict__ Ri,
                            const float* __restrict__ Ro, const float* __restrict__ W,
                            const float* __restrict__ te, const float* __restrict__ tn,
                            int N, int E) {
    int t = blockIdx.x * blockDim.x + threadIdx.x;
    int quarter = (N * E) >> 2;
    if (t < quarter) {
        float4 v = ((const float4*)Ro)[t];
        int base = t * 4;
        if (v.x > 0.5f) g_snd[ base      % E] =  base      / E;
        if (v.y > 0.5f) g_snd[(base + 1) % E] = (base + 1) / E;
        if (v.z > 0.5f) g_snd[(base + 2) % E] = (base + 2) / E;
        if (v.w > 0.5f) g_snd[(base + 3) % E] = (base + 3) / E;
    } else if (t < 2 * quarter) {
        int u = t - quarter;
        float4 v = ((const float4*)Ri)[u];
        int base = u * 4;
        if (v.x > 0.5f) g_rcv[ base      % E] =  base      / E;
        if (v.y > 0.5f) g_rcv[(base + 1) % E] = (base + 1) / E;
        if (v.z > 0.5f) g_rcv[(base + 2) % E] = (base + 2) / E;
        if (v.w > 0.5f) g_rcv[(base + 3) % E] = (base + 3) / E;
    }
    if (t < N * HS) { g_mi[t] = 0.f; g_mo[t] = 0.f; }
    if (t < 4) g_bar[t] = 0u;
    if (t < N) {
        float x0 = X[t * 3 + 0], x1 = X[t * 3 + 1], x2 = X[t * 3 + 2];
        float z0 = x0 * W[0] + x1 * W[2] + x2 * W[4];
        float z1 = x0 * W[1] + x1 * W[3] + x2 * W[5];
        const float TWOPI = 6.283185307179586f;
        g_Hd[t * HS + 0] = TWOPI / (1.f + __expf(-z0));
        g_Hd[t * HS + 1] = TWOPI / (1.f + __expf(-z1));
        g_Hd[t * HS + 2] = x0;
        g_Hd[t * HS + 3] = x1;
        g_Hd[t * HS + 4] = x2;
        g_Hd[t * HS + 5] = 0.f;
        g_Hd[t * HS + 6] = 0.f;
        g_Hd[t * HS + 7] = 0.f;
    }
    if (t >= 3072 && t < 3081) {        // edge rotation constants te[10..18]
        int i = t - 3072;
        float ss, cc; sincosf(te[10 + i], &ss, &cc);
        g_ecs[i] = make_float2(cc, ss);
    }
    if (t >= 3104 && t < 3115) {        // node rotation constants
        int i = t - 3104; float ang = 0.f;
        switch (i) {
            case 0:  ang = tn[16]; break;
            case 1:  ang = tn[19]; break;
            case 2:  ang = tn[14]; break;
            case 3:  ang = tn[15]; break;
            case 4:  ang = tn[20]; break;
            case 5:  ang = tn[23] + tn[26]; break;
            case 6:  ang = tn[29]; break;
            case 7:  ang = 0.5f * tn[25]; break;
            case 8:  ang = tn[17] + tn[21]; break;
            case 9:  ang = tn[24] + tn[27]; break;
            case 10: ang = tn[30]; break;
        }
        float ss, cc; sincosf(ang, &ss, &cc);
        g_ncs[i] = make_float2(cc, ss);
    }
    if (t == 3136) g_nsum[0] = tn[13] + tn[18] + tn[22];
    if (t == 3137) g_nsum[1] = tn[14] + tn[19] + tn[28];
}

// ---------------- fused persistent kernel: edge/node x 5 phases --------------
__global__ void __launch_bounds__(TPB) gnn_fused(
    const float* __restrict__ te, const float* __restrict__ tn,
    float* __restrict__ out, int N, int E) {
    int tid = blockIdx.x * TPB + threadIdx.x;
    bool isEdge = tid < E;
    bool isNode = tid < N;

    // hoist per-edge invariants into registers (written by prep kernel)
    int sn = 0, rc = 0;
    float tr[10];
    float2 T[9];
    if (isEdge) {
        sn = g_snd[tid]; rc = g_rcv[tid];
#pragma unroll
        for (int j = 0; j < 10; j++) tr[j] = te[j];
#pragma unroll
        for (int j = 0; j < 9; j++) T[j] = g_ecs[j];
    }

    for (int it = 0; it < 3; it++) {
        // ================= edge phase =================
        if (isEdge) {
            float h[10];
            {   // L2 reads (bypass non-coherent L1 across phases)
                float4 v0 = __ldcg((const float4*)&g_Hd[sn * HS]);
                float4 v1 = __ldcg((const float4*)&g_Hd[rc * HS]);
                h[0] = v0.x; h[1] = v0.y; h[2] = v0.z; h[3] = v0.w;
                h[4] = __ldcg(&g_Hd[sn * HS + 4]);
                h[5] = v1.x; h[6] = v1.y; h[7] = v1.z; h[8] = v1.w;
                h[9] = __ldcg(&g_Hd[rc * HS + 4]);
            }
            float cA[10], sA[10];
#pragma unroll
            for (int j = 0; j < 10; j++) __sincosf(h[j] + tr[j], &sA[j], &cA[j]);

            // q1: init, cx0,1, ry t10
            float z1 = cA[1] * cA[0], x1 = sA[1]; rot(z1, x1, T[0].x, T[0].y);
            // q2: init, cx3,2, ry t11, cx1,2, ry t14
            float z2 = cA[2] * cA[3], x2 = sA[2]; rot(z2, x2, T[1].x, T[1].y);
            z2 *= z1;                             rot(z2, x2, T[4].x, T[4].y);
            // q4: init, cx5,4, ry t15, cx2,4, ry t16
            float z4 = cA[4] * cA[5], x4 = sA[4]; rot(z4, x4, T[5].x, T[5].y);
            z4 *= z2;                             rot(z4, x4, T[6].x, T[6].y);
            // q9: init, cx8,9, ry t13
            float z9 = cA[9] * cA[8], x9 = sA[9]; rot(z9, x9, T[3].x, T[3].y);
            // q7: init, cx6,7, t12, cx9,7, t17, cx4,7, t18 -> measure
            float z7 = cA[7] * cA[6], x7 = sA[7]; rot(z7, x7, T[2].x, T[2].y);
            z7 *= z9;                             rot(z7, x7, T[7].x, T[7].y);
            z7 *= z4;                             rot(z7, x7, T[8].x, T[8].y);

            float e = 0.5f * (1.0f - z7);
            if (it < 2) {
#pragma unroll
                for (int j = 0; j < 5; j++) atomicAdd(&g_mi[rc * HS + j], e * h[j]);
#pragma unroll
                for (int j = 0; j < 5; j++) atomicAdd(&g_mo[sn * HS + j], e * h[5 + j]);
            } else {
                out[tid] = e;
            }
        }
        if (it == 2) break;
        gbar(2 * it);

        // ================= node phase =================
        if (isNode) {
            int n = tid;
            float f[15];
            {
                float4 a = __ldcg((const float4*)&g_mi[n * HS]);
                f[0] = a.x; f[1] = a.y; f[2] = a.z; f[3] = a.w;
                f[4] = __ldcg(&g_mi[n * HS + 4]);
                float4 b = __ldcg((const float4*)&g_mo[n * HS]);
                f[5] = b.x; f[6] = b.y; f[7] = b.z; f[8] = b.w;
                f[9] = __ldcg(&g_mo[n * HS + 4]);
                float4 d = __ldcg((const float4*)&g_Hd[n * HS]);
                f[10] = d.x; f[11] = d.y; f[12] = d.z; f[13] = d.w;
                f[14] = __ldcg(&g_Hd[n * HS + 4]);
            }
            // re-zero messages for the next edge round (exclusive slots)
            *(float4*)&g_mi[n * HS] = make_float4(0.f, 0.f, 0.f, 0.f);
            g_mi[n * HS + 4] = 0.f;
            *(float4*)&g_mo[n * HS] = make_float4(0.f, 0.f, 0.f, 0.f);
            g_mo[n * HS + 4] = 0.f;

            float2 R;
            // ---- component B: <Z10> ----
            float cA10, sA10; __sincosf(f[10] + tn[10], &sA10, &cA10);
            float z11 = __cosf(f[11] + tn[11]);
            float z13 = __cosf(f[13] + g_nsum[0]);
            float z14 = __cosf(f[14] + g_nsum[1]);
            float zb = cA10 * z11, xb = sA10;      // init, cx11,10
            R = g_ncs[8];  rot(zb, xb, R.x, R.y);  // t17+t21
            zb *= z13;                             // cx13,10
            R = g_ncs[9];  rot(zb, xb, R.x, R.y);  // t24+t27
            zb *= z14;                             // cx14,10
            R = g_ncs[10]; rot(zb, xb, R.x, R.y);  // t30
            float zB = zb;

            // ---- component A: <Z5>, 2-branch dephasing of q1 ----
            float a0 = 0.5f * (f[0] + tn[0]);
            float a1 = 0.5f * (f[1] + tn[1]);
            float t15h = 0.5f * tn[15];
            float cg0, sg0; __sincosf(t15h + a1, &sg0, &cg0);
            float cd, sd;   __sincosf(t15h - a1, &sd, &cd);
            float cg1 = -sd, sg1 = cd;
            float ca0, sa0; __sincosf(a0, &sa0, &ca0);
            float2 R25 = g_ncs[7];
            float w[2], zw[2];
            {
                float p0 = ca0 * cg0, p1 = sa0 * cg1;
                float q0 = p0 * R25.x - p1 * R25.y, q1 = p1 * R25.x + p0 * R25.y;
                w[0] = q0 * q0 + q1 * q1;  zw[0] = q0 * q0 - q1 * q1;
                p0 = ca0 * sg0;  p1 = sa0 * sg1;
                q0 = p0 * R25.x - p1 * R25.y;  q1 = p1 * R25.x + p0 * R25.y;
                w[1] = q0 * q0 + q1 * q1;  zw[1] = q0 * q0 - q1 * q1;
            }
            // q2: init, cx3,2, t16, X^{beta1}, t19
            float cA2, sA2; __sincosf(f[2] + tn[2], &sA2, &cA2);
            float z3 = __cosf(f[3] + tn[3]);
            float z2 = cA2 * z3, x2 = sA2;
            R = g_ncs[0]; rot(z2, x2, R.x, R.y);                    // t16
            float2 R19 = g_ncs[1];
            float z2b0 =  z2, x2b0 = x2; rot(z2b0, x2b0, R19.x, R19.y);
            float z2b1 = -z2, x2b1 = x2; rot(z2b1, x2b1, R19.x, R19.y);
            // q6: init, cx7,6, t15
            float cA6, sA6; __sincosf(f[6] + tn[6], &sA6, &cA6);
            float z7c = __cosf(f[7] + tn[7]);
            float z6 = cA6 * z7c, x6 = sA6;
            R = g_ncs[3]; rot(z6, x6, R.x, R.y);                    // t15
            // q5 common: init, cx4,5, t14, cx6,5, t20
            float cA5, sA5; __sincosf(f[5] + tn[5], &sA5, &cA5);
            float z4c = __cosf(f[4] + tn[4]);
            float z5 = cA5 * z4c, x5 = sA5;
            R = g_ncs[2]; rot(z5, x5, R.x, R.y);                    // t14
            z5 *= z6;
            R = g_ncs[4]; rot(z5, x5, R.x, R.y);                    // t20
            float2 R2326 = g_ncs[5], R29 = g_ncs[6];
            float zA = 0.f;
#pragma unroll
            for (int b = 0; b < 2; b++) {
                float z = z5 * (b ? z2b1 : z2b0), x = x5;           // cx2,5
                rot(z, x, R2326.x, R2326.y);                        // t23 + t26
                float zp = z * zw[b], xp = x * w[b];                // cx0,5 (weighted)
                zA += zp * R29.x - xp * R29.y;                      // t29, take z
            }
            const float PI_F = 3.14159265358979f;
            g_Hd[n * HS + 0] = PI_F * (1.f - zA);
            g_Hd[n * HS + 1] = PI_F * (1.f - zB);
        }
        gbar(2 * it + 1);
    }
}

// ---------------- launch (graph-capturable, 2 kernels) -----------------------
extern "C" void kernel_launch(void* const* d_in, const int* in_sizes, int n_in,
                              void* d_out, int out_size) {
    const float* X  = (const float*)d_in[0];
    const float* Ri = (const float*)d_in[1];
    const float* Ro = (const float*)d_in[2];
    const float* W  = (const float*)d_in[3];
    const float* te = (const float*)d_in[4];
    const float* tn = (const float*)d_in[5];
    int N = in_sizes[0] / 3;
    int E = in_sizes[1] / N;

    int pg = (2 * ((N * E) / 4) + 255) / 256;   // float4 scan of Ro + Ri
    prep_kernel<<<pg, 256>>>(X, Ri, Ro, W, te, tn, N, E);
    gnn_fused<<<NBLOCKS, TPB>>>(te, tn, (float*)d_out, N, E);
}